// round 12
// baseline (speedup 1.0000x reference)
#include <cuda_runtime.h>
#include <cuda_fp16.h>
#include <cuda_fp8.h>
#include <cstdint>

#define NN 8192
#define TT 100

constexpr int TPB  = 256;
constexpr int NBLK = 512;    // 512 blocks x 16 cols, full K per block
constexpr int NCT  = 8;      // cached tiles per warp (of 32)
constexpr int NST  = 32 - NCT; // streamed tiles (24, multiple of ring depth 8)

// Scratch (device globals: no allocation allowed in kernel_launch)
__device__ __align__(16) unsigned char g_tsA[(size_t)NN * NN]; // tiled e4m3 fragments (64 MB)
__device__ __align__(16) unsigned char g_Vq[NN];               // e4m3 stage-V vector
__device__ float    g_diag[NN];
__device__ float    g_state[3 * NN];                            // initial U | I | V (SoA)
__device__ unsigned g_arrive;
__device__ unsigned g_gen;

// ---------------------------------------------------------------------------
// Convert ts -> e4m3, tiled for mma.m16n8k32 A-fragments. (verified layout)
// ---------------------------------------------------------------------------
__global__ void convert_kernel(const float* __restrict__ ts) {
    __shared__ unsigned sQ[32 * 32];   // 32 rows x 128 cols as bytes
    const int bid  = blockIdx.x;
    const int j    = bid & 255;        // 32-row group
    const int cc   = bid >> 8;         // 128-col chunk
    const int row0 = j * 32, col0 = cc * 128;
    const int tid  = threadIdx.x;

#pragma unroll
    for (int u = 0; u < 4; ++u) {
        int idx = u * 256 + tid;
        int rr  = idx >> 5;
        int cf  = idx & 31;
        float4 f = *reinterpret_cast<const float4*>(ts + (size_t)(row0 + rr) * NN + col0 + cf * 4);
        __nv_fp8x2_storage_t lo = __nv_cvt_float2_to_fp8x2(
            make_float2(f.x * 8192.f, f.y * 8192.f), __NV_SATFINITE, __NV_E4M3);
        __nv_fp8x2_storage_t hi = __nv_cvt_float2_to_fp8x2(
            make_float2(f.z * 8192.f, f.w * 8192.f), __NV_SATFINITE, __NV_E4M3);
        sQ[rr * 32 + cf] = (unsigned)lo | ((unsigned)hi << 16);
    }
    __syncthreads();

    const int w = tid >> 5, lane = tid & 31, g = lane >> 2, tg = lane & 3;
    const int c = 16 * w + g;
    auto B = [&](int r, int col) -> unsigned {
        return (sQ[r * 32 + (col >> 2)] >> ((col & 3) * 8)) & 0xffu;
    };
    unsigned a0 = B(4*tg+0, c)      | (B(4*tg+1, c)      << 8) | (B(4*tg+2, c)      << 16) | (B(4*tg+3, c)      << 24);
    unsigned a1 = B(4*tg+0, c+8)    | (B(4*tg+1, c+8)    << 8) | (B(4*tg+2, c+8)    << 16) | (B(4*tg+3, c+8)    << 24);
    unsigned a2 = B(16+4*tg+0, c)   | (B(16+4*tg+1, c)   << 8) | (B(16+4*tg+2, c)   << 16) | (B(16+4*tg+3, c)   << 24);
    unsigned a3 = B(16+4*tg+0, c+8) | (B(16+4*tg+1, c+8) << 8) | (B(16+4*tg+2, c+8) << 16) | (B(16+4*tg+3, c+8) << 24);

    const int i_tile = cc * 8 + w;
    size_t addr = ((size_t)i_tile * 256 + j) * 512 + (size_t)lane * 16;
    *reinterpret_cast<uint4*>(g_tsA + addr) = make_uint4(a0, a1, a2, a3);
}

__global__ void init_kernel(const float* __restrict__ x0,
                            const float* __restrict__ ts,
                            float* __restrict__ out) {
    int i = blockIdx.x * blockDim.x + threadIdx.x;
    if (i < NN) {
        float V0 = fabsf(x0[3 * i + 2]);
        g_state[i]          = fabsf(x0[3 * i + 0]);
        g_state[NN + i]     = fabsf(x0[3 * i + 1]);
        g_state[2 * NN + i] = V0;
        g_Vq[i] = (unsigned char)__nv_cvt_float_to_fp8(V0, __NV_SATFINITE, __NV_E4M3);
        float d = ts[(size_t)i * NN + i] * 8192.f;
        __nv_fp8_storage_t s8 = __nv_cvt_float_to_fp8(d, __NV_SATFINITE, __NV_E4M3);
        __half_raw hr = __nv_cvt_fp8_to_halfraw(s8, __NV_E4M3);
        g_diag[i] = __half2float(__half(hr)) * (1.f / 8192.f);
    }
    if (i < 3 * TT) out[i] = 0.f;
    if (i == 0)     { g_arrive = 0u; g_gen = 0u; }
}

__device__ __forceinline__ float sigmoidf_(float z) {
    return 1.f / (1.f + expf(-z));
}

__global__ void out0_kernel(const float* __restrict__ W, const float* __restrict__ bb,
                            const float* __restrict__ slope, const float* __restrict__ thr,
                            float* __restrict__ out) {
    int i = blockIdx.x * blockDim.x + threadIdx.x;
    float U = g_state[i], I = g_state[NN + i], V = g_state[2 * NN + i];
    float s[3];
#pragma unroll
    for (int m = 0; m < 3; ++m) {
        float lin = W[3 * m + 0] * U + W[3 * m + 1] * I + W[3 * m + 2] * V + bb[m];
        s[m] = sigmoidf_(slope[m] * (lin - thr[m]));
    }
#pragma unroll
    for (int o = 16; o > 0; o >>= 1) {
        s[0] += __shfl_down_sync(0xffffffffu, s[0], o);
        s[1] += __shfl_down_sync(0xffffffffu, s[1], o);
        s[2] += __shfl_down_sync(0xffffffffu, s[2], o);
    }
    __shared__ float red[3][8];
    int warp = threadIdx.x >> 5, lane = threadIdx.x & 31;
    if (lane == 0) { red[0][warp] = s[0]; red[1][warp] = s[1]; red[2][warp] = s[2]; }
    __syncthreads();
    if (threadIdx.x == 0) {
        float t0 = 0.f, t1 = 0.f, t2 = 0.f;
#pragma unroll
        for (int w = 0; w < 8; ++w) { t0 += red[0][w]; t1 += red[1][w]; t2 += red[2][w]; }
        atomicAdd(out + 0 * TT, t0 * (1.f / 8192.f));
        atomicAdd(out + 1 * TT, t1 * (1.f / 8192.f));
        atomicAdd(out + 2 * TT, t2 * (1.f / 8192.f));
    }
}

__device__ __forceinline__ void mma_e4m3(float& c0, float& c1, float& c2, float& c3,
                                         const uint4& a, unsigned b0, unsigned b1) {
    asm volatile(
        "mma.sync.aligned.m16n8k32.row.col.f32.e4m3.e4m3.f32 "
        "{%0,%1,%2,%3}, {%4,%5,%6,%7}, {%8,%9}, {%0,%1,%2,%3};\n"
        : "+f"(c0), "+f"(c1), "+f"(c2), "+f"(c3)
        : "r"(a.x), "r"(a.y), "r"(a.z), "r"(a.w), "r"(b0), "r"(b1));
}

// Grid-wide barrier (all NBLK blocks co-resident by construction).
__device__ __forceinline__ void grid_barrier(unsigned gen) {
    __syncthreads();
    if (threadIdx.x == 0) {
        __threadfence();
        unsigned old = atomicAdd(&g_arrive, 1u);
        if (old == NBLK - 1) {
            g_arrive = 0u;
            __threadfence();
            atomicExch(&g_gen, gen);
        } else {
            unsigned cur;
            do {
                asm volatile("ld.global.acquire.gpu.u32 %0, [%1];" : "=r"(cur) : "l"(&g_gen));
            } while (cur < gen);
        }
    }
    __syncthreads();
}

// ---------------------------------------------------------------------------
// Persistent solver. Block b owns cols [16b,16b+16) over full K.
// Warp w's first NCT tiles live in SMEM (filled once); remaining NST tiles
// stream from L2 via a ring that prefetches across the stage barrier.
// ---------------------------------------------------------------------------
__global__ void __launch_bounds__(TPB, 4) solve_kernel(
    const float* __restrict__ times,
    const float* __restrict__ betas, const float* __restrict__ deltas,
    const float* __restrict__ cs, const float* __restrict__ ps,
    const float* __restrict__ W, const float* __restrict__ bb,
    const float* __restrict__ slope, const float* __restrict__ thr,
    float* __restrict__ out) {

    const int tid  = threadIdx.x;
    const int bid  = blockIdx.x;
    const int w = tid >> 5, lane = tid & 31, g = lane >> 2, tg = lane & 3;

    __shared__ uint4 sMat[8 * NCT * 32];  // 32 KB: warp w, tile t at (w*NCT+t)*32+lane
    __shared__ uint4 sVq4[512];           // warp w owns uint4 [w*64, w*64+64)
    __shared__ float sC[8][17];           // per-warp partial C (16 cols)
    __shared__ float sU[16], sI[16], sV[16];
    __shared__ float sK[9][16];           // k1..k3 x {U,I,V}
    __shared__ float sPar[5][16];         // |beta|,|delta|,|p|,|c|,diag

    unsigned* sVq32 = reinterpret_cast<unsigned*>(sVq4);

    if (tid < 16) {
        int i = bid * 16 + tid;
        sU[tid] = g_state[i];
        sI[tid] = g_state[NN + i];
        sV[tid] = g_state[2 * NN + i];
        sPar[0][tid] = fabsf(betas[i]);
        sPar[1][tid] = fabsf(deltas[i]);
        sPar[2][tid] = fabsf(ps[i]);
        sPar[3][tid] = fabsf(cs[i]);
        sPar[4][tid] = g_diag[i];
    }

    // Warp's contiguous fragment stream: tiles (bid, w*32 .. w*32+31)
    const uint4* mp = reinterpret_cast<const uint4*>(g_tsA)
        + ((size_t)bid * 256 + w * 32) * 32 + lane;
    const int vbase = w * 256;        // u32 index of this warp's 1024 rows

    // fill smem-cached tiles 0..NCT-1 (once)
#pragma unroll
    for (int t = 0; t < NCT; ++t)
        sMat[(w * NCT + t) * 32 + lane] = mp[(size_t)t * 32];

    // preload stream ring with tiles NCT..NCT+7
    uint4 q[8];
#pragma unroll
    for (int b = 0; b < 8; ++b) q[b] = mp[(size_t)(NCT + b) * 32];
    __syncthreads();

    for (int step = 0; step < TT - 1; ++step) {
        const float h   = times[step + 1] - times[step];
        const float hd6 = h * (1.f / 6.f);

        for (int stage = 1; stage <= 4; ++stage) {
            const float ah = (stage == 1) ? 0.f : ((stage == 4) ? h : 0.5f * h);

            // ---- warp-local Vq fill ----
            {
                const uint4* gv = reinterpret_cast<const uint4*>(g_Vq);
                sVq4[w * 64 + lane]      = gv[w * 64 + lane];
                sVq4[w * 64 + 32 + lane] = gv[w * 64 + 32 + lane];
                __syncwarp();
            }

            // ---- Phase A: interleave 8 cached-tile MMAs with 24 streamed ----
            float c0 = 0.f, c1 = 0.f, c2 = 0.f, c3 = 0.f;
#pragma unroll
            for (int k = 0; k < NCT; ++k) {
                {   // cached tile k (LDS)
                    uint4 cu = sMat[(w * NCT + k) * 32 + lane];
                    unsigned b0 = sVq32[vbase + k * 8 + tg];
                    unsigned b1 = sVq32[vbase + k * 8 + 4 + tg];
                    mma_e4m3(c0, c1, c2, c3, cu, b0, b1);
                }
#pragma unroll
                for (int u = 0; u < 3; ++u) {
                    int s  = k * 3 + u;          // streamed index 0..23
                    int jj = NCT + s;            // tile index
                    uint4 cu = q[s & 7];
                    q[s & 7] = mp[(size_t)(NCT + ((s + 8) % NST)) * 32];  // wraps for next stage
                    unsigned b0 = sVq32[vbase + jj * 8 + tg];
                    unsigned b1 = sVq32[vbase + jj * 8 + 4 + tg];
                    mma_e4m3(c0, c1, c2, c3, cu, b0, b1);
                }
            }
            if (tg == 0) { sC[w][g] = c0; sC[w][g + 8] = c2; }
            __syncthreads();

            // ---- Phase B: 16 threads, one column each, all-smem ----
            float s0 = 0.f, s1 = 0.f, s2 = 0.f;
            if (tid < 16) {
                const int i = bid * 16 + tid;
                float coup = 0.f;
#pragma unroll
                for (int ww = 0; ww < 8; ++ww) coup += sC[ww][tid];

                float U = sU[tid], I = sI[tid], V = sV[tid];
                if (stage > 1) {
                    const int pb = (stage - 2) * 3;
                    U = fmaf(ah, sK[pb + 0][tid], U);
                    I = fmaf(ah, sK[pb + 1][tid], I);
                    V = fmaf(ah, sK[pb + 2][tid], V);
                }
                float cp  = coup * (1.f / 8192.f) - sPar[4][tid] * V;
                float inf = sPar[0][tid] * U * V;
                float kU  = -inf;
                float kI  = inf - sPar[1][tid] * I;
                float kV  = sPar[2][tid] * I - sPar[3][tid] * V + cp;

                float vnext;
                if (stage < 4) {
                    const int cb = (stage - 1) * 3;
                    sK[cb + 0][tid] = kU;
                    sK[cb + 1][tid] = kI;
                    sK[cb + 2][tid] = kV;
                    float an = (stage == 3) ? h : 0.5f * h;   // a for next stage
                    vnext = fmaf(an, kV, sV[tid]);
                } else {
                    float nU = sU[tid] + hd6 * (sK[0][tid] + 2.f * sK[3][tid] + 2.f * sK[6][tid] + kU);
                    float nI = sI[tid] + hd6 * (sK[1][tid] + 2.f * sK[4][tid] + 2.f * sK[7][tid] + kI);
                    float nV = sV[tid] + hd6 * (sK[2][tid] + 2.f * sK[5][tid] + 2.f * sK[8][tid] + kV);
                    sU[tid] = nU;
                    sI[tid] = nI;
                    sV[tid] = nV;
                    vnext = nV;
#pragma unroll
                    for (int m = 0; m < 3; ++m) {
                        float lin = W[3 * m + 0] * nU + W[3 * m + 1] * nI + W[3 * m + 2] * nV + bb[m];
                        float sg  = sigmoidf_(slope[m] * (lin - thr[m]));
                        if (m == 0) s0 += sg; else if (m == 1) s1 += sg; else s2 += sg;
                    }
                }
                g_Vq[i] = (unsigned char)__nv_cvt_float_to_fp8(vnext, __NV_SATFINITE, __NV_E4M3);
            }

            if (stage == 4 && tid < 16) {
#pragma unroll
                for (int o = 8; o > 0; o >>= 1) {
                    s0 += __shfl_down_sync(0xffffu, s0, o);
                    s1 += __shfl_down_sync(0xffffu, s1, o);
                    s2 += __shfl_down_sync(0xffffu, s2, o);
                }
                if (tid == 0) {
                    atomicAdd(out + 0 * TT + step + 1, s0 * (1.f / 8192.f));
                    atomicAdd(out + 1 * TT + step + 1, s1 * (1.f / 8192.f));
                    atomicAdd(out + 2 * TT + step + 1, s2 * (1.f / 8192.f));
                }
            }

            // single stage boundary sync
            if (!(step == TT - 2 && stage == 4))
                grid_barrier((unsigned)(step * 4 + stage));
        }
    }
}

// ---------------------------------------------------------------------------
extern "C" void kernel_launch(void* const* d_in, const int* in_sizes, int n_in,
                              void* d_out, int out_size) {
    const float* times  = (const float*)d_in[0];
    const float* x0     = (const float*)d_in[1];
    const float* betas  = (const float*)d_in[2];
    const float* deltas = (const float*)d_in[3];
    const float* cs     = (const float*)d_in[4];
    const float* ps     = (const float*)d_in[5];
    const float* ts     = (const float*)d_in[6];
    const float* W      = (const float*)d_in[7];
    const float* b      = (const float*)d_in[8];
    const float* slope  = (const float*)d_in[9];
    const float* thr    = (const float*)d_in[10];
    float* out = (float*)d_out;

    convert_kernel<<<256 * 64, 256>>>(ts);
    init_kernel<<<NN / 256, 256>>>(x0, ts, out);
    out0_kernel<<<NN / 256, 256>>>(W, b, slope, thr, out);
    solve_kernel<<<NBLK, TPB>>>(times, betas, deltas, cs, ps, W, b, slope, thr, out);
}

// round 15
// speedup vs baseline: 1.0029x; 1.0029x over previous
#include <cuda_runtime.h>
#include <cuda_fp16.h>
#include <cuda_fp8.h>
#include <cstdint>

#define NN 8192
#define TT 100

constexpr int TPB  = 256;
constexpr int NBLK = 512;    // 512 blocks x 16 cols, full K per block

// Scratch (device globals: no allocation allowed in kernel_launch)
__device__ __align__(16) unsigned char g_tsA[(size_t)NN * NN]; // tiled e4m3 fragments (64 MB)
__device__ __align__(16) unsigned char g_Vq[NN];               // e4m3 stage-V vector
__device__ float    g_diag[NN];
__device__ float    g_state[3 * NN];                            // initial U | I | V (SoA)
__device__ unsigned g_arrive;
__device__ unsigned g_gen;

// ---------------------------------------------------------------------------
// Convert ts -> e4m3, tiled for mma.m16n8k32 A-fragments. (verified layout)
// ---------------------------------------------------------------------------
__global__ void convert_kernel(const float* __restrict__ ts) {
    __shared__ unsigned sQ[32 * 32];   // 32 rows x 128 cols as bytes
    const int bid  = blockIdx.x;
    const int j    = bid & 255;        // 32-row group
    const int cc   = bid >> 8;         // 128-col chunk
    const int row0 = j * 32, col0 = cc * 128;
    const int tid  = threadIdx.x;

#pragma unroll
    for (int u = 0; u < 4; ++u) {
        int idx = u * 256 + tid;
        int rr  = idx >> 5;
        int cf  = idx & 31;
        float4 f = *reinterpret_cast<const float4*>(ts + (size_t)(row0 + rr) * NN + col0 + cf * 4);
        __nv_fp8x2_storage_t lo = __nv_cvt_float2_to_fp8x2(
            make_float2(f.x * 8192.f, f.y * 8192.f), __NV_SATFINITE, __NV_E4M3);
        __nv_fp8x2_storage_t hi = __nv_cvt_float2_to_fp8x2(
            make_float2(f.z * 8192.f, f.w * 8192.f), __NV_SATFINITE, __NV_E4M3);
        sQ[rr * 32 + cf] = (unsigned)lo | ((unsigned)hi << 16);
    }
    __syncthreads();

    const int w = tid >> 5, lane = tid & 31, g = lane >> 2, tg = lane & 3;
    const int c = 16 * w + g;
    auto B = [&](int r, int col) -> unsigned {
        return (sQ[r * 32 + (col >> 2)] >> ((col & 3) * 8)) & 0xffu;
    };
    unsigned a0 = B(4*tg+0, c)      | (B(4*tg+1, c)      << 8) | (B(4*tg+2, c)      << 16) | (B(4*tg+3, c)      << 24);
    unsigned a1 = B(4*tg+0, c+8)    | (B(4*tg+1, c+8)    << 8) | (B(4*tg+2, c+8)    << 16) | (B(4*tg+3, c+8)    << 24);
    unsigned a2 = B(16+4*tg+0, c)   | (B(16+4*tg+1, c)   << 8) | (B(16+4*tg+2, c)   << 16) | (B(16+4*tg+3, c)   << 24);
    unsigned a3 = B(16+4*tg+0, c+8) | (B(16+4*tg+1, c+8) << 8) | (B(16+4*tg+2, c+8) << 16) | (B(16+4*tg+3, c+8) << 24);

    const int i_tile = cc * 8 + w;
    size_t addr = ((size_t)i_tile * 256 + j) * 512 + (size_t)lane * 16;
    *reinterpret_cast<uint4*>(g_tsA + addr) = make_uint4(a0, a1, a2, a3);
}

__global__ void init_kernel(const float* __restrict__ x0,
                            const float* __restrict__ ts,
                            float* __restrict__ out) {
    int i = blockIdx.x * blockDim.x + threadIdx.x;
    if (i < NN) {
        float V0 = fabsf(x0[3 * i + 2]);
        g_state[i]          = fabsf(x0[3 * i + 0]);
        g_state[NN + i]     = fabsf(x0[3 * i + 1]);
        g_state[2 * NN + i] = V0;
        g_Vq[i] = (unsigned char)__nv_cvt_float_to_fp8(V0, __NV_SATFINITE, __NV_E4M3);
        float d = ts[(size_t)i * NN + i] * 8192.f;
        __nv_fp8_storage_t s8 = __nv_cvt_float_to_fp8(d, __NV_SATFINITE, __NV_E4M3);
        __half_raw hr = __nv_cvt_fp8_to_halfraw(s8, __NV_E4M3);
        g_diag[i] = __half2float(__half(hr)) * (1.f / 8192.f);
    }
    if (i < 3 * TT) out[i] = 0.f;
    if (i == 0)     { g_arrive = 0u; g_gen = 0u; }
}

__device__ __forceinline__ float sigmoidf_(float z) {
    return 1.f / (1.f + expf(-z));
}

__global__ void out0_kernel(const float* __restrict__ W, const float* __restrict__ bb,
                            const float* __restrict__ slope, const float* __restrict__ thr,
                            float* __restrict__ out) {
    int i = blockIdx.x * blockDim.x + threadIdx.x;
    float U = g_state[i], I = g_state[NN + i], V = g_state[2 * NN + i];
    float s[3];
#pragma unroll
    for (int m = 0; m < 3; ++m) {
        float lin = W[3 * m + 0] * U + W[3 * m + 1] * I + W[3 * m + 2] * V + bb[m];
        s[m] = sigmoidf_(slope[m] * (lin - thr[m]));
    }
#pragma unroll
    for (int o = 16; o > 0; o >>= 1) {
        s[0] += __shfl_down_sync(0xffffffffu, s[0], o);
        s[1] += __shfl_down_sync(0xffffffffu, s[1], o);
        s[2] += __shfl_down_sync(0xffffffffu, s[2], o);
    }
    __shared__ float red[3][8];
    int warp = threadIdx.x >> 5, lane = threadIdx.x & 31;
    if (lane == 0) { red[0][warp] = s[0]; red[1][warp] = s[1]; red[2][warp] = s[2]; }
    __syncthreads();
    if (threadIdx.x == 0) {
        float t0 = 0.f, t1 = 0.f, t2 = 0.f;
#pragma unroll
        for (int w = 0; w < 8; ++w) { t0 += red[0][w]; t1 += red[1][w]; t2 += red[2][w]; }
        atomicAdd(out + 0 * TT, t0 * (1.f / 8192.f));
        atomicAdd(out + 1 * TT, t1 * (1.f / 8192.f));
        atomicAdd(out + 2 * TT, t2 * (1.f / 8192.f));
    }
}

__device__ __forceinline__ void mma_e4m3(float& c0, float& c1, float& c2, float& c3,
                                         const uint4& a, unsigned b0, unsigned b1) {
    asm volatile(
        "mma.sync.aligned.m16n8k32.row.col.f32.e4m3.e4m3.f32 "
        "{%0,%1,%2,%3}, {%4,%5,%6,%7}, {%8,%9}, {%0,%1,%2,%3};\n"
        : "+f"(c0), "+f"(c1), "+f"(c2), "+f"(c3)
        : "r"(a.x), "r"(a.y), "r"(a.z), "r"(a.w), "r"(b0), "r"(b1));
}

// Grid-wide barrier (all NBLK blocks co-resident by construction).
__device__ __forceinline__ void grid_barrier(unsigned gen) {
    __syncthreads();
    if (threadIdx.x == 0) {
        __threadfence();
        unsigned old = atomicAdd(&g_arrive, 1u);
        if (old == NBLK - 1) {
            g_arrive = 0u;
            __threadfence();
            atomicExch(&g_gen, gen);
        } else {
            unsigned cur;
            do {
                asm volatile("ld.global.acquire.gpu.u32 %0, [%1];" : "=r"(cur) : "l"(&g_gen));
            } while (cur < gen);
        }
    }
    __syncthreads();
}

// ---------------------------------------------------------------------------
// Persistent solver (R11 geometry). Block b owns cols [16b,16b+16) over full K.
// Warp w: row chunk w*1024. Warp-private Vq smem slice PERMUTED so each
// tile's B operand pair is one LDS.64. Matrix ring (depth 8) prefetches
// across the stage barrier.
// ---------------------------------------------------------------------------
__global__ void __launch_bounds__(TPB, 4) solve_kernel(
    const float* __restrict__ times,
    const float* __restrict__ betas, const float* __restrict__ deltas,
    const float* __restrict__ cs, const float* __restrict__ ps,
    const float* __restrict__ W, const float* __restrict__ bb,
    const float* __restrict__ slope, const float* __restrict__ thr,
    float* __restrict__ out) {

    const int tid  = threadIdx.x;
    const int bid  = blockIdx.x;
    const int w = tid >> 5, lane = tid & 31, g = lane >> 2, tg = lane & 3;

    __shared__ uint2 sVqP[8][128];    // warp-private permuted Vq: [w][jj*4+tg]
    __shared__ float sC[8][17];       // per-warp partial C (16 cols)
    __shared__ float sU[16], sI[16], sV[16];
    __shared__ float sK[9][16];       // k1..k3 x {U,I,V}
    __shared__ float sPar[5][16];     // |beta|,|delta|,|p|,|c|,diag

    if (tid < 16) {
        int i = bid * 16 + tid;
        sU[tid] = g_state[i];
        sI[tid] = g_state[NN + i];
        sV[tid] = g_state[2 * NN + i];
        sPar[0][tid] = fabsf(betas[i]);
        sPar[1][tid] = fabsf(deltas[i]);
        sPar[2][tid] = fabsf(ps[i]);
        sPar[3][tid] = fabsf(cs[i]);
        sPar[4][tid] = g_diag[i];
    }

    // Warp's contiguous fragment stream: tiles (bid, w*32 .. w*32+31)
    const uint4* mp = reinterpret_cast<const uint4*>(g_tsA)
        + ((size_t)bid * 256 + w * 32) * 32 + lane;

    // preload fragment ring (stage-invariant stream)
    uint4 q[8];
#pragma unroll
    for (int b = 0; b < 8; ++b) q[b] = mp[(size_t)b * 32];
    __syncthreads();

    for (int step = 0; step < TT - 1; ++step) {
        const float h   = times[step + 1] - times[step];
        const float hd6 = h * (1.f / 6.f);

        for (int stage = 1; stage <= 4; ++stage) {
            const float ah = (stage == 1) ? 0.f : ((stage == 4) ? h : 0.5f * h);

            // ---- warp-private PERMUTED Vq fill ----
            // src word s = jj*8 + c*4 + tg  ->  dest word jj*8 + tg*2 + c
            // (warp w's 1024 rows = g_Vq words [w*256, w*256+256))
            {
                const uint4* gv = reinterpret_cast<const uint4*>(g_Vq);
                uint4 gv0 = gv[w * 64 + lane];
                uint4 gv1 = gv[w * 64 + 32 + lane];
                unsigned* sw = reinterpret_cast<unsigned*>(sVqP[w]);
                int b0w = (lane >> 1) * 8 + (lane & 1);
                sw[b0w + 0] = gv0.x; sw[b0w + 2] = gv0.y;
                sw[b0w + 4] = gv0.z; sw[b0w + 6] = gv0.w;
                int m1  = lane + 32;
                int b1w = (m1 >> 1) * 8 + (m1 & 1);
                sw[b1w + 0] = gv1.x; sw[b1w + 2] = gv1.y;
                sw[b1w + 4] = gv1.z; sw[b1w + 6] = gv1.w;
                __syncwarp();
            }

            // ---- Phase A: 32 MMAs; ring refill wraps to next stage's tiles ----
            float c0 = 0.f, c1 = 0.f, c2 = 0.f, c3 = 0.f;
#pragma unroll
            for (int it = 0; it < 4; ++it) {
#pragma unroll
                for (int b = 0; b < 8; ++b) {
                    uint4 cu = q[b];
                    q[b] = mp[(size_t)((((it + 1) & 3) * 8 + b)) * 32];
                    int jj = it * 8 + b;
                    uint2 bv = sVqP[w][jj * 4 + tg];
                    mma_e4m3(c0, c1, c2, c3, cu, bv.x, bv.y);
                }
            }
            if (tg == 0) { sC[w][g] = c0; sC[w][g + 8] = c2; }
            __syncthreads();

            // ---- Phase B: 16 threads, one column each, all-smem ----
            float s0 = 0.f, s1 = 0.f, s2 = 0.f;
            if (tid < 16) {
                const int i = bid * 16 + tid;
                float coup = 0.f;
#pragma unroll
                for (int ww = 0; ww < 8; ++ww) coup += sC[ww][tid];

                float U = sU[tid], I = sI[tid], V = sV[tid];
                if (stage > 1) {
                    const int pb = (stage - 2) * 3;
                    U = fmaf(ah, sK[pb + 0][tid], U);
                    I = fmaf(ah, sK[pb + 1][tid], I);
                    V = fmaf(ah, sK[pb + 2][tid], V);
                }
                float cp  = coup * (1.f / 8192.f) - sPar[4][tid] * V;
                float inf = sPar[0][tid] * U * V;
                float kU  = -inf;
                float kI  = inf - sPar[1][tid] * I;
                float kV  = sPar[2][tid] * I - sPar[3][tid] * V + cp;

                float vnext;
                if (stage < 4) {
                    const int cb = (stage - 1) * 3;
                    sK[cb + 0][tid] = kU;
                    sK[cb + 1][tid] = kI;
                    sK[cb + 2][tid] = kV;
                    float an = (stage == 3) ? h : 0.5f * h;   // a for next stage
                    vnext = fmaf(an, kV, sV[tid]);
                } else {
                    float nU = sU[tid] + hd6 * (sK[0][tid] + 2.f * sK[3][tid] + 2.f * sK[6][tid] + kU);
                    float nI = sI[tid] + hd6 * (sK[1][tid] + 2.f * sK[4][tid] + 2.f * sK[7][tid] + kI);
                    float nV = sV[tid] + hd6 * (sK[2][tid] + 2.f * sK[5][tid] + 2.f * sK[8][tid] + kV);
                    sU[tid] = nU;
                    sI[tid] = nI;
                    sV[tid] = nV;
                    vnext = nV;
#pragma unroll
                    for (int m = 0; m < 3; ++m) {
                        float lin = W[3 * m + 0] * nU + W[3 * m + 1] * nI + W[3 * m + 2] * nV + bb[m];
                        float sg  = sigmoidf_(slope[m] * (lin - thr[m]));
                        if (m == 0) s0 += sg; else if (m == 1) s1 += sg; else s2 += sg;
                    }
                }
                g_Vq[i] = (unsigned char)__nv_cvt_float_to_fp8(vnext, __NV_SATFINITE, __NV_E4M3);
            }

            if (stage == 4 && tid < 16) {
#pragma unroll
                for (int o = 8; o > 0; o >>= 1) {
                    s0 += __shfl_down_sync(0xffffu, s0, o);
                    s1 += __shfl_down_sync(0xffffu, s1, o);
                    s2 += __shfl_down_sync(0xffffu, s2, o);
                }
                if (tid == 0) {
                    atomicAdd(out + 0 * TT + step + 1, s0 * (1.f / 8192.f));
                    atomicAdd(out + 1 * TT + step + 1, s1 * (1.f / 8192.f));
                    atomicAdd(out + 2 * TT + step + 1, s2 * (1.f / 8192.f));
                }
            }

            // single stage boundary sync
            if (!(step == TT - 2 && stage == 4))
                grid_barrier((unsigned)(step * 4 + stage));
        }
    }
}

// ---------------------------------------------------------------------------
extern "C" void kernel_launch(void* const* d_in, const int* in_sizes, int n_in,
                              void* d_out, int out_size) {
    const float* times  = (const float*)d_in[0];
    const float* x0     = (const float*)d_in[1];
    const float* betas  = (const float*)d_in[2];
    const float* deltas = (const float*)d_in[3];
    const float* cs     = (const float*)d_in[4];
    const float* ps     = (const float*)d_in[5];
    const float* ts     = (const float*)d_in[6];
    const float* W      = (const float*)d_in[7];
    const float* b      = (const float*)d_in[8];
    const float* slope  = (const float*)d_in[9];
    const float* thr    = (const float*)d_in[10];
    float* out = (float*)d_out;

    convert_kernel<<<256 * 64, 256>>>(ts);
    init_kernel<<<NN / 256, 256>>>(x0, ts, out);
    out0_kernel<<<NN / 256, 256>>>(W, b, slope, thr, out);
    solve_kernel<<<NBLK, TPB>>>(times, betas, deltas, cs, ps, W, b, slope, thr, out);
}